// round 8
// baseline (speedup 1.0000x reference)
#include <cuda_runtime.h>

// TropicalLeNet fully fused, one launch. R8: warp-skewed channel loops
// (de-correlate stalls across warps) + float4 weight loads with aligned,
// quarter-warp-conflict-free layouts.

__global__ void __launch_bounds__(512, 2)
lenet_kernel(const float* __restrict__ input,
             const float* __restrict__ w1,
             const float* __restrict__ w2,
             const float* __restrict__ fw1, const float* __restrict__ fb1,
             const float* __restrict__ fw2, const float* __restrict__ fb2,
             const float* __restrict__ fw3, const float* __restrict__ fb3,
             float* __restrict__ out)
{
    const int b   = blockIdx.x;
    const int tid = threadIdx.x;
    const int warp = tid >> 5, lane = tid & 31;

    __shared__ __align__(16) float xp[32 * 34];     // padded input, stride 34
    __shared__ __align__(16) float w1s[3 * 28];     // wait: 6 filters -> 6*28
    __shared__ __align__(16) float w1s2[3 * 28];    // split to keep both cg banks simple
    __shared__ __align__(16) float w2s[16 * 172];   // [oc]*172 + [c]*28 + t
    __shared__ __align__(16) float p1s[6 * 320];    // [c]*320 + r*22 + col
    __shared__ __align__(16) float p2s[400];
    __shared__ __align__(16) float h1[120];
    __shared__ __align__(16) float h2[84];

    // ---- stage 0: stage input (zero-padded) + conv weights ----
    {
        const float* inb = input + b * 784;
        #pragma unroll
        for (int k = 0; k < 2; k++) {
            int i = tid + 512 * k;
            int h = i >> 5, w = i & 31;
            bool in = (h >= 2) && (h < 30) && (w >= 2) && (w < 30);
            xp[h * 34 + w] = in ? inb[(h - 2) * 28 + (w - 2)] : 0.0f;
        }
        if (tid < 150) {
            int ch = tid / 25, t = tid % 25;
            if (ch < 3) w1s[ch * 28 + t] = w1[tid];
            else        w1s2[(ch - 3) * 28 + t] = w1[tid];
        }
        for (int i = tid; i < 2400; i += 512) {
            int f = i / 25, t = i % 25;           // f = oc*6 + c
            w2s[(f / 6) * 172 + (f % 6) * 28 + t] = w2[i];
        }
    }
    __syncthreads();

    // ---- stage 1: min-plus conv1 + avgpool -> p1s ----
    // 392 threads: sp = tid%196, cg = tid/196 -> channels 3cg..3cg+2,
    // iterated in warp-skewed order.
    if (tid < 392) {
        const int sp = tid % 196, cg = tid / 196;
        const int i = sp / 14, j = sp % 14;
        const int base = i * 68 + 2 * j;          // (2i)*34 + 2j (even)
        const float* wbank = cg ? w1s2 : w1s;

        float win[6][6];
        #pragma unroll
        for (int u = 0; u < 6; u++) {
            const float2* r = (const float2*)&xp[base + u * 34];
            float2 a = r[0], bb = r[1], c2 = r[2];
            win[u][0] = a.x;  win[u][1] = a.y;
            win[u][2] = bb.x; win[u][3] = bb.y;
            win[u][4] = c2.x; win[u][5] = c2.y;
        }

        #pragma unroll 1
        for (int cc = 0; cc < 3; cc++) {
            const int c = (cc + warp) % 3;        // warp-skewed
            float wr[25];
            {
                const float4* wq = (const float4*)&wbank[c * 28];
                #pragma unroll
                for (int q = 0; q < 6; q++) {
                    float4 v = wq[q];
                    wr[4 * q]     = v.x; wr[4 * q + 1] = v.y;
                    wr[4 * q + 2] = v.z; wr[4 * q + 3] = v.w;
                }
                wr[24] = wbank[c * 28 + 24];
            }
            float m00 = win[0][0] + wr[0];
            float m01 = win[0][1] + wr[0];
            float m10 = win[1][0] + wr[0];
            float m11 = win[1][1] + wr[0];
            #pragma unroll
            for (int t = 1; t < 25; t++) {
                const int du = t / 5, dv = t % 5;
                const float w = wr[t];
                m00 = fminf(m00, win[du][dv]         + w);
                m01 = fminf(m01, win[du][dv + 1]     + w);
                m10 = fminf(m10, win[du + 1][dv]     + w);
                m11 = fminf(m11, win[du + 1][dv + 1] + w);
            }
            p1s[(3 * cg + c) * 320 + i * 22 + j] =
                0.25f * ((m00 + m01) + (m10 + m11));
        }
    }
    __syncthreads();

    // ---- stage 2: max-plus conv2 + avgpool -> p2s[400] ----
    // oc = tid&15, sp = tid>>4 (sp<25 active); warp-skewed channel order.
    {
        const int oc = tid & 15, sp = tid >> 4;
        if (sp < 25) {
            const int i = sp / 5, j = sp % 5;
            const int pbase = i * 44 + 2 * j;     // (2i)*22 + 2j (even)
            const float* wsoc = &w2s[oc * 172];

            float acc = 0.0f;
            #pragma unroll 1
            for (int cc = 0; cc < 6; cc++) {
                const int c = (cc + warp) % 6;    // warp-skewed

                float win[6][6];
                #pragma unroll
                for (int u = 0; u < 6; u++) {
                    const float2* r =
                        (const float2*)&p1s[c * 320 + pbase + u * 22];
                    float2 a = r[0], bb = r[1], c2 = r[2];
                    win[u][0] = a.x;  win[u][1] = a.y;
                    win[u][2] = bb.x; win[u][3] = bb.y;
                    win[u][4] = c2.x; win[u][5] = c2.y;
                }

                float wr[25];
                {
                    const float4* wq = (const float4*)&wsoc[c * 28];
                    #pragma unroll
                    for (int q = 0; q < 6; q++) {
                        float4 v = wq[q];
                        wr[4 * q]     = v.x; wr[4 * q + 1] = v.y;
                        wr[4 * q + 2] = v.z; wr[4 * q + 3] = v.w;
                    }
                    wr[24] = wsoc[c * 28 + 24];
                }

                float m00 = win[0][0] + wr[0];
                float m01 = win[0][1] + wr[0];
                float m10 = win[1][0] + wr[0];
                float m11 = win[1][1] + wr[0];
                #pragma unroll
                for (int t = 1; t < 25; t++) {
                    const int du = t / 5, dv = t % 5;
                    const float w = wr[t];
                    m00 = fmaxf(m00, win[du][dv]         + w);
                    m01 = fmaxf(m01, win[du][dv + 1]     + w);
                    m10 = fmaxf(m10, win[du + 1][dv]     + w);
                    m11 = fmaxf(m11, win[du + 1][dv + 1] + w);
                }
                acc += (m00 + m01) + (m10 + m11);
            }
            p2s[oc * 25 + sp] = 0.25f * acc;
        }
    }
    __syncthreads();

    // ---- fc1: 400 -> 120, relu. 60 output-pair tasks over 16 warps.
    for (int t = warp; t < 60; t += 16) {
        const int o0 = 2 * t, o1 = o0 + 1;
        const float4* wa = (const float4*)(fw1 + o0 * 400);
        const float4* wb = (const float4*)(fw1 + o1 * 400);
        const float4* xv = (const float4*)p2s;
        float sa = 0.0f, sb = 0.0f;
        #pragma unroll
        for (int k = 0; k < 3; k++) {
            const int i4 = lane + 32 * k;
            float4 v = xv[i4], a = wa[i4], c = wb[i4];
            sa = fmaf(v.x, a.x, sa); sa = fmaf(v.y, a.y, sa);
            sa = fmaf(v.z, a.z, sa); sa = fmaf(v.w, a.w, sa);
            sb = fmaf(v.x, c.x, sb); sb = fmaf(v.y, c.y, sb);
            sb = fmaf(v.z, c.z, sb); sb = fmaf(v.w, c.w, sb);
        }
        if (lane < 4) {
            const int i4 = 96 + lane;
            float4 v = xv[i4], a = wa[i4], c = wb[i4];
            sa = fmaf(v.x, a.x, sa); sa = fmaf(v.y, a.y, sa);
            sa = fmaf(v.z, a.z, sa); sa = fmaf(v.w, a.w, sa);
            sb = fmaf(v.x, c.x, sb); sb = fmaf(v.y, c.y, sb);
            sb = fmaf(v.z, c.z, sb); sb = fmaf(v.w, c.w, sb);
        }
        #pragma unroll
        for (int off = 16; off; off >>= 1) {
            sa += __shfl_xor_sync(0xffffffffu, sa, off);
            sb += __shfl_xor_sync(0xffffffffu, sb, off);
        }
        if (lane == 0) {
            h1[o0] = fmaxf(sa + fb1[o0], 0.0f);
            h1[o1] = fmaxf(sb + fb1[o1], 0.0f);
        }
    }
    __syncthreads();

    // ---- fc2: 120 -> 84, relu. 42 tasks; 30 float4/row.
    for (int t = warp; t < 42; t += 16) {
        const int o0 = 2 * t, o1 = o0 + 1;
        const float4* wa = (const float4*)(fw2 + o0 * 120);
        const float4* wb = (const float4*)(fw2 + o1 * 120);
        const float4* xv = (const float4*)h1;
        float sa = 0.0f, sb = 0.0f;
        if (lane < 30) {
            float4 v = xv[lane], a = wa[lane], c = wb[lane];
            sa = fmaf(v.x, a.x, sa); sa = fmaf(v.y, a.y, sa);
            sa = fmaf(v.z, a.z, sa); sa = fmaf(v.w, a.w, sa);
            sb = fmaf(v.x, c.x, sb); sb = fmaf(v.y, c.y, sb);
            sb = fmaf(v.z, c.z, sb); sb = fmaf(v.w, c.w, sb);
        }
        #pragma unroll
        for (int off = 16; off; off >>= 1) {
            sa += __shfl_xor_sync(0xffffffffu, sa, off);
            sb += __shfl_xor_sync(0xffffffffu, sb, off);
        }
        if (lane == 0) {
            h2[o0] = fmaxf(sa + fb2[o0], 0.0f);
            h2[o1] = fmaxf(sb + fb2[o1], 0.0f);
        }
    }
    __syncthreads();

    // ---- fc3: 84 -> 10. warps 0..9, one output each.
    if (warp < 10) {
        const int o = warp;
        const float4* wr = (const float4*)(fw3 + o * 84);
        const float4* xv = (const float4*)h2;
        float s = 0.0f;
        if (lane < 21) {
            float4 v = xv[lane], a = wr[lane];
            s = fmaf(v.x, a.x, s); s = fmaf(v.y, a.y, s);
            s = fmaf(v.z, a.z, s); s = fmaf(v.w, a.w, s);
        }
        #pragma unroll
        for (int off = 16; off; off >>= 1) s += __shfl_xor_sync(0xffffffffu, s, off);
        if (lane == 0) out[b * 10 + o] = s + fb3[o];
    }
}

extern "C" void kernel_launch(void* const* d_in, const int* in_sizes, int n_in,
                              void* d_out, int out_size)
{
    const float* input = (const float*)d_in[0];
    const float* w1    = (const float*)d_in[1];
    const float* w2    = (const float*)d_in[2];
    const float* fw1   = (const float*)d_in[3];
    const float* fb1   = (const float*)d_in[4];
    const float* fw2   = (const float*)d_in[5];
    const float* fb2   = (const float*)d_in[6];
    const float* fw3   = (const float*)d_in[7];
    const float* fb3   = (const float*)d_in[8];

    const int B = in_sizes[0] / 784;  // 256

    lenet_kernel<<<B, 512>>>(input, w1, w2, fw1, fb1, fw2, fb2, fw3, fb3,
                             (float*)d_out);
}

// round 9
// speedup vs baseline: 1.0777x; 1.0777x over previous
#include <cuda_runtime.h>

// TropicalLeNet fused, one launch. R9: rolling-row window streaming in both
// convs (peak liveness ~47 regs vs ~65 -> ptxas can hide LDS latency),
// plus L1 prefetch of fc weights from conv-phase idle warps.

__device__ __forceinline__ void loadrow(float* dst, const float* p) {
    const float2* r = (const float2*)p;
    float2 a = r[0], b = r[1], c = r[2];
    dst[0] = a.x; dst[1] = a.y;
    dst[2] = b.x; dst[3] = b.y;
    dst[4] = c.x; dst[5] = c.y;
}

__global__ void __launch_bounds__(512, 2)
lenet_kernel(const float* __restrict__ input,
             const float* __restrict__ w1,
             const float* __restrict__ w2,
             const float* __restrict__ fw1, const float* __restrict__ fb1,
             const float* __restrict__ fw2, const float* __restrict__ fb2,
             const float* __restrict__ fw3, const float* __restrict__ fb3,
             float* __restrict__ out)
{
    const int b   = blockIdx.x;
    const int tid = threadIdx.x;
    const int warp = tid >> 5, lane = tid & 31;

    __shared__ __align__(16) float xp[32 * 34];     // padded input, stride 34
    __shared__ __align__(16) float w1s[6 * 28];     // [ch]*28 + t
    __shared__ __align__(16) float w2s[16 * 172];   // [oc]*172 + [c]*28 + t
    __shared__ __align__(16) float p1s[6 * 320];    // [c]*320 + r*22 + col
    __shared__ __align__(16) float p2s[400];
    __shared__ __align__(16) float h1[120];
    __shared__ __align__(16) float h2[84];

    // ---- stage 0: stage input (zero-padded) + conv weights ----
    {
        const float* inb = input + b * 784;
        #pragma unroll
        for (int k = 0; k < 2; k++) {
            int i = tid + 512 * k;
            int h = i >> 5, w = i & 31;
            bool in = (h >= 2) && (h < 30) && (w >= 2) && (w < 30);
            xp[h * 34 + w] = in ? inb[(h - 2) * 28 + (w - 2)] : 0.0f;
        }
        if (tid < 150) w1s[(tid / 25) * 28 + tid % 25] = w1[tid];
        for (int i = tid; i < 2400; i += 512) {
            int f = i / 25, t = i % 25;           // f = oc*6 + c
            w2s[(f / 6) * 172 + (f % 6) * 28 + t] = w2[i];
        }
    }
    __syncthreads();

    // ---- stage 1: min-plus conv1 + avgpool -> p1s ----
    // 392 threads: sp = tid%196, cg = tid/196 -> channels 3cg..3cg+2.
    if (tid < 392) {
        const int sp = tid % 196, cg = tid / 196;
        const int i = sp / 14, j = sp % 14;
        const float* rbase = &xp[i * 68 + 2 * j];  // row r at rbase + r*34

        #pragma unroll 1
        for (int cc = 0; cc < 3; cc++) {
            const int ch = 3 * cg + cc;
            float wr[25];
            {
                const float4* wq = (const float4*)&w1s[ch * 28];
                #pragma unroll
                for (int q = 0; q < 6; q++) {
                    float4 v = wq[q];
                    wr[4 * q]     = v.x; wr[4 * q + 1] = v.y;
                    wr[4 * q + 2] = v.z; wr[4 * q + 3] = v.w;
                }
                wr[24] = w1s[ch * 28 + 24];
            }

            float ra[6], rb[6], rc[6];
            loadrow(ra, rbase);
            loadrow(rb, rbase + 34);

            const float INF = __int_as_float(0x7f800000);
            float m00 = INF, m01 = INF, m10 = INF, m11 = INF;

            #define C1TAPS(du, X, Y)                                        \
                {                                                           \
                    _Pragma("unroll")                                       \
                    for (int dv = 0; dv < 5; dv++) {                        \
                        const float w = wr[(du) * 5 + dv];                  \
                        m00 = fminf(m00, X[dv]     + w);                    \
                        m01 = fminf(m01, X[dv + 1] + w);                    \
                        m10 = fminf(m10, Y[dv]     + w);                    \
                        m11 = fminf(m11, Y[dv + 1] + w);                    \
                    }                                                       \
                }

            loadrow(rc, rbase + 2 * 34);
            C1TAPS(0, ra, rb)
            loadrow(ra, rbase + 3 * 34);
            C1TAPS(1, rb, rc)
            loadrow(rb, rbase + 4 * 34);
            C1TAPS(2, rc, ra)
            loadrow(rc, rbase + 5 * 34);
            C1TAPS(3, ra, rb)
            C1TAPS(4, rb, rc)
            #undef C1TAPS

            p1s[ch * 320 + i * 22 + j] = 0.25f * ((m00 + m01) + (m10 + m11));
        }
    } else if (tid >= 416) {
        // warps 13-15: prefetch fw1 (192000 B = 1500 lines) into L1.
        const int t = tid - 416;                  // 0..95
        #pragma unroll
        for (int k = 0; k < 16; k++) {
            int line = t * 16 + k;
            if (line < 1500) {
                const char* p = (const char*)fw1 + line * 128;
                asm volatile("prefetch.global.L1 [%0];" :: "l"(p));
            }
        }
    }
    __syncthreads();

    // ---- stage 2: max-plus conv2 + avgpool -> p2s[400] ----
    // oc = tid&15, sp = tid>>4 (sp<25 active).
    {
        const int oc = tid & 15, sp = tid >> 4;
        if (sp < 25) {
            const int i = sp / 5, j = sp % 5;
            const float* wsoc = &w2s[oc * 172];

            float acc = 0.0f;
            #pragma unroll 1
            for (int c = 0; c < 6; c++) {
                float wr[25];
                {
                    const float4* wq = (const float4*)&wsoc[c * 28];
                    #pragma unroll
                    for (int q = 0; q < 6; q++) {
                        float4 v = wq[q];
                        wr[4 * q]     = v.x; wr[4 * q + 1] = v.y;
                        wr[4 * q + 2] = v.z; wr[4 * q + 3] = v.w;
                    }
                    wr[24] = wsoc[c * 28 + 24];
                }

                const float* rbase = &p1s[c * 320 + i * 44 + 2 * j];

                float ra[6], rb[6], rc[6];
                loadrow(ra, rbase);
                loadrow(rb, rbase + 22);

                const float NINF = __int_as_float(0xff800000);
                float m00 = NINF, m01 = NINF, m10 = NINF, m11 = NINF;

                #define C2TAPS(du, X, Y)                                    \
                    {                                                       \
                        _Pragma("unroll")                                   \
                        for (int dv = 0; dv < 5; dv++) {                    \
                            const float w = wr[(du) * 5 + dv];              \
                            m00 = fmaxf(m00, X[dv]     + w);                \
                            m01 = fmaxf(m01, X[dv + 1] + w);                \
                            m10 = fmaxf(m10, Y[dv]     + w);                \
                            m11 = fmaxf(m11, Y[dv + 1] + w);                \
                        }                                                   \
                    }

                loadrow(rc, rbase + 2 * 22);
                C2TAPS(0, ra, rb)
                loadrow(ra, rbase + 3 * 22);
                C2TAPS(1, rb, rc)
                loadrow(rb, rbase + 4 * 22);
                C2TAPS(2, rc, ra)
                loadrow(rc, rbase + 5 * 22);
                C2TAPS(3, ra, rb)
                C2TAPS(4, rb, rc)
                #undef C2TAPS

                acc += (m00 + m01) + (m10 + m11);
            }
            p2s[oc * 25 + sp] = 0.25f * acc;
        } else if (tid >= 416) {
            // warps 13-15: prefetch fw2 (40320 B = 315 lines) into L1.
            const int t = tid - 416;
            #pragma unroll
            for (int k = 0; k < 4; k++) {
                int line = t * 4 + k;
                if (line < 315) {
                    const char* p = (const char*)fw2 + line * 128;
                    asm volatile("prefetch.global.L1 [%0];" :: "l"(p));
                }
            }
        }
    }
    __syncthreads();

    // ---- fc1: 400 -> 120, relu. 60 output-pair tasks over 16 warps.
    for (int t = warp; t < 60; t += 16) {
        const int o0 = 2 * t, o1 = o0 + 1;
        const float4* wa = (const float4*)(fw1 + o0 * 400);
        const float4* wb = (const float4*)(fw1 + o1 * 400);
        const float4* xv = (const float4*)p2s;
        float sa = 0.0f, sb = 0.0f;
        #pragma unroll
        for (int k = 0; k < 3; k++) {
            const int i4 = lane + 32 * k;
            float4 v = xv[i4], a = wa[i4], c = wb[i4];
            sa = fmaf(v.x, a.x, sa); sa = fmaf(v.y, a.y, sa);
            sa = fmaf(v.z, a.z, sa); sa = fmaf(v.w, a.w, sa);
            sb = fmaf(v.x, c.x, sb); sb = fmaf(v.y, c.y, sb);
            sb = fmaf(v.z, c.z, sb); sb = fmaf(v.w, c.w, sb);
        }
        if (lane < 4) {
            const int i4 = 96 + lane;
            float4 v = xv[i4], a = wa[i4], c = wb[i4];
            sa = fmaf(v.x, a.x, sa); sa = fmaf(v.y, a.y, sa);
            sa = fmaf(v.z, a.z, sa); sa = fmaf(v.w, a.w, sa);
            sb = fmaf(v.x, c.x, sb); sb = fmaf(v.y, c.y, sb);
            sb = fmaf(v.z, c.z, sb); sb = fmaf(v.w, c.w, sb);
        }
        #pragma unroll
        for (int off = 16; off; off >>= 1) {
            sa += __shfl_xor_sync(0xffffffffu, sa, off);
            sb += __shfl_xor_sync(0xffffffffu, sb, off);
        }
        if (lane == 0) {
            h1[o0] = fmaxf(sa + fb1[o0], 0.0f);
            h1[o1] = fmaxf(sb + fb1[o1], 0.0f);
        }
    }
    __syncthreads();

    // ---- fc2: 120 -> 84, relu. 42 tasks; 30 float4/row.
    for (int t = warp; t < 42; t += 16) {
        const int o0 = 2 * t, o1 = o0 + 1;
        const float4* wa = (const float4*)(fw2 + o0 * 120);
        const float4* wb = (const float4*)(fw2 + o1 * 120);
        const float4* xv = (const float4*)h1;
        float sa = 0.0f, sb = 0.0f;
        if (lane < 30) {
            float4 v = xv[lane], a = wa[lane], c = wb[lane];
            sa = fmaf(v.x, a.x, sa); sa = fmaf(v.y, a.y, sa);
            sa = fmaf(v.z, a.z, sa); sa = fmaf(v.w, a.w, sa);
            sb = fmaf(v.x, c.x, sb); sb = fmaf(v.y, c.y, sb);
            sb = fmaf(v.z, c.z, sb); sb = fmaf(v.w, c.w, sb);
        }
        #pragma unroll
        for (int off = 16; off; off >>= 1) {
            sa += __shfl_xor_sync(0xffffffffu, sa, off);
            sb += __shfl_xor_sync(0xffffffffu, sb, off);
        }
        if (lane == 0) {
            h2[o0] = fmaxf(sa + fb2[o0], 0.0f);
            h2[o1] = fmaxf(sb + fb2[o1], 0.0f);
        }
    }
    __syncthreads();

    // ---- fc3: 84 -> 10. warps 0..9, one output each.
    if (warp < 10) {
        const int o = warp;
        const float4* wr = (const float4*)(fw3 + o * 84);
        const float4* xv = (const float4*)h2;
        float s = 0.0f;
        if (lane < 21) {
            float4 v = xv[lane], a = wr[lane];
            s = fmaf(v.x, a.x, s); s = fmaf(v.y, a.y, s);
            s = fmaf(v.z, a.z, s); s = fmaf(v.w, a.w, s);
        }
        #pragma unroll
        for (int off = 16; off; off >>= 1) s += __shfl_xor_sync(0xffffffffu, s, off);
        if (lane == 0) out[b * 10 + o] = s + fb3[o];
    }
}

extern "C" void kernel_launch(void* const* d_in, const int* in_sizes, int n_in,
                              void* d_out, int out_size)
{
    const float* input = (const float*)d_in[0];
    const float* w1    = (const float*)d_in[1];
    const float* w2    = (const float*)d_in[2];
    const float* fw1   = (const float*)d_in[3];
    const float* fb1   = (const float*)d_in[4];
    const float* fw2   = (const float*)d_in[5];
    const float* fb2   = (const float*)d_in[6];
    const float* fw3   = (const float*)d_in[7];
    const float* fb3   = (const float*)d_in[8];

    const int B = in_sizes[0] / 784;  // 256

    lenet_kernel<<<B, 512>>>(input, w1, w2, fw1, fb1, fw2, fb2, fw3, fb3,
                             (float*)d_out);
}